// round 6
// baseline (speedup 1.0000x reference)
#include <cuda_runtime.h>
#include <cstdint>
#include <cstddef>

// ---------------------------------------------------------------------------
// Constants: decomposition filters (from reference)
// ---------------------------------------------------------------------------
__constant__ float c_lo[8] = {
    -0.010597401784997278f,  0.032883011666982945f,  0.030841381835986965f,
    -0.18703481171888114f,  -0.02798376941698385f,   0.6308807679295904f,
     0.7148465705525415f,    0.23037781330885523f};
__constant__ float c_hi[8] = {
    -0.23037781330885523f,   0.7148465705525415f,   -0.6308807679295904f,
    -0.02798376941698385f,   0.18703481171888114f,   0.030841381835986965f,
    -0.032883011666982945f, -0.010597401784997278f};

// Effective projection: Weff[k][o], k = c*8 + j (24), o (128). Row-major, o contiguous.
__device__ float g_weff[24 * 128];

// ---------------------------------------------------------------------------
// Exact single-level pywt dwt, mode='symmetric'
// ---------------------------------------------------------------------------
__device__ __forceinline__ void dwt_dev(const float* a, int n, float* lo, float* hi) {
    int m = (n + 7) / 2;
    for (int i = 0; i < m; ++i) {
        float accL = 0.f, accH = 0.f;
        for (int f = 0; f < 8; ++f) {
            int t = (1 + 2 * i + f) - 7;
            if (t < 0) t = -1 - t;
            else if (t >= n) t = 2 * n - 1 - t;
            float xv = a[t];
            accL += xv * c_lo[7 - f];
            accH += xv * c_hi[7 - f];
        }
        lo[i] = accL;
        hi[i] = accH;
    }
}

// ---------------------------------------------------------------------------
// Init kernel: build M (28x8) via basis vectors, fold into Weff.
// ---------------------------------------------------------------------------
__global__ void init_weff_kernel(const float* __restrict__ W) {
    __shared__ float sM[28][8];
    int t = threadIdx.x;
    if (t < 8) {
        float win[8];
        #pragma unroll
        for (int i = 0; i < 8; ++i) win[i] = (i == t) ? 1.f : 0.f;
        float cA[7], cD[7], aa[7], ad[7], da[7], dd[7];
        dwt_dev(win, 8, cA, cD);
        dwt_dev(cA, 7, aa, ad);
        dwt_dev(cD, 7, da, dd);
        for (int i = 0; i < 7; ++i) {
            sM[i][t]      = aa[i];
            sM[7 + i][t]  = ad[i];
            sM[14 + i][t] = dd[i];
            sM[21 + i][t] = da[i];
        }
    }
    __syncthreads();
    int o = threadIdx.x;  // 0..127
    for (int c = 0; c < 3; ++c) {
        for (int j = 0; j < 8; ++j) {
            float s = 0.f;
            #pragma unroll
            for (int k = 0; k < 28; ++k) s += sM[k][j] * W[o * 84 + c * 28 + k];
            g_weff[(c * 8 + j) * 128 + o] = s;
        }
    }
}

// ---------------------------------------------------------------------------
// Packed f32x2 helpers
// ---------------------------------------------------------------------------
__device__ __forceinline__ uint64_t ffma2(uint64_t a, uint64_t b, uint64_t c) {
    uint64_t d;
    asm("fma.rn.f32x2 %0, %1, %2, %3;" : "=l"(d) : "l"(a), "l"(b), "l"(c));
    return d;
}
__device__ __forceinline__ uint64_t bcast2(float x) {
    uint64_t d;
    unsigned xi = __float_as_uint(x);
    asm("mov.b64 %0, {%1, %1};" : "=l"(d) : "r"(xi));
    return d;
}
__device__ __forceinline__ float2 unpack2(uint64_t u) {
    float2 f;
    asm("mov.b64 {%0, %1}, %2;" : "=f"(f.x), "=f"(f.y) : "l"(u));
    return f;
}
__device__ __forceinline__ float f4_get(const float4& v, int i) {
    switch (i) {
        case 0: return v.x;
        case 1: return v.y;
        case 2: return v.z;
        default: return v.w;
    }
}

// ---------------------------------------------------------------------------
// Main kernel (Weff in registers, 2 o-cols per lane, 3 CTAs/SM):
//   grid = (2, 25, 32), block = 256 (8 warps)
//   Block handles 512 consecutive p-rows x 128 o-cols of one (b, v).
//   Warp w (0..3):  cols [0,64),   rows [w*128, (w+1)*128)
//   Warp w (4..7):  cols [64,128), rows [(w-4)*128, (w-3)*128)
//   Lane l owns cols colbase + 2l .. 2l+1.
// ---------------------------------------------------------------------------
static constexpr int ROWS_PB = 512;
static constexpr int XLEN = 4 * ROWS_PB + 4;   // 2052 samples per channel

__global__ void __launch_bounds__(256, 3)
wavelet_embed_kernel(const float* __restrict__ x, float* __restrict__ out) {
    __shared__ float s_x[3 * XLEN];    // 24.6 KB

    const int tid  = threadIdx.x;
    const int half = blockIdx.x;   // 0..1
    const int v    = blockIdx.y;   // 0..24
    const int b    = blockIdx.z;   // 0..31
    const int p0   = half * ROWS_PB;
    const int t0   = 4 * p0;

    // ---- stage x: t in [t0, t0+2051], 3 channels, fixed v, edge-clamp ----
    const float* xb = x + ((size_t)b * 3) * 4096 * 25 + v;
    for (int i = tid; i < 3 * XLEN; i += 256) {
        int c  = i / XLEN;
        int tt = i - c * XLEN;
        int t  = t0 + tt;
        if (t > 4095) t = 4095;
        s_x[i] = xb[((size_t)c * 4096 + t) * 25];
    }

    const int lane    = tid & 31;
    const int wid     = tid >> 5;
    const int colhalf = wid >> 2;           // 0 or 1
    const int wrow    = wid & 3;            // 0..3
    const int col0    = colhalf * 64 + 2 * lane;

    // ---- this lane's 2-column Weff slice in registers (48 regs) ----
    uint64_t w[24];
    #pragma unroll
    for (int k = 0; k < 24; ++k)
        w[k] = *reinterpret_cast<const uint64_t*>(g_weff + k * 128 + col0);

    __syncthreads();

    const size_t rowg = (size_t)b * 25600 + (size_t)v * 1024 + p0;
    const int rbase = wrow * 128;           // this warp's first row

    for (int g = 0; g < 32; ++g) {
        const int r0 = rbase + g * 4;

        uint64_t acc[4];
        #pragma unroll
        for (int rr = 0; rr < 4; ++rr) acc[rr] = 0ull;

        #pragma unroll
        for (int c = 0; c < 3; ++c) {
            // 5 overlapping warp-uniform float4 loads cover 4 rows' windows:
            // row rr uses xv[rr] (j=0..3) and xv[rr+1] (j=4..7)
            const float4* xp = reinterpret_cast<const float4*>(s_x + c * XLEN);
            float4 xv[5];
            #pragma unroll
            for (int i = 0; i < 5; ++i) xv[i] = xp[r0 + i];

            #pragma unroll
            for (int j = 0; j < 8; ++j) {
                const int k = c * 8 + j;
                #pragma unroll
                for (int rr = 0; rr < 4; ++rr) {
                    const float xs = (j < 4) ? f4_get(xv[rr], j) : f4_get(xv[rr + 1], j - 4);
                    acc[rr] = ffma2(bcast2(xs), w[k], acc[rr]);
                }
            }
        }

        #pragma unroll
        for (int rr = 0; rr < 4; ++rr) {
            float2 a = unpack2(acc[rr]);
            *reinterpret_cast<float2*>(out + (rowg + r0 + rr) * 128 + col0) =
                make_float2(a.x, a.y);
        }
    }
}

// ---------------------------------------------------------------------------
// Launch
// ---------------------------------------------------------------------------
extern "C" void kernel_launch(void* const* d_in, const int* in_sizes, int n_in,
                              void* d_out, int out_size) {
    const float* x = (const float*)d_in[0];  // (32, 3, 4096, 25) fp32
    const float* W = (const float*)d_in[1];  // (128, 84) fp32
    float* out = (float*)d_out;              // (32, 25600, 128) fp32

    init_weff_kernel<<<1, 128>>>(W);
    dim3 grid(2, 25, 32);
    wavelet_embed_kernel<<<grid, 256>>>(x, out);
}